// round 13
// baseline (speedup 1.0000x reference)
#include <cuda_runtime.h>

#define NW 14
#define NSTATE (1 << NW)        // 16384 amplitudes
#define NTHREADS 1024
#define NWARPS (NTHREADS / 32)

// ==================== compile-time GF(2) machinery ====================
struct CT {
    unsigned rowA[NW];      // rows of A
    unsigned colAinv[NW];   // columns of A^-1 (pair masks)
    unsigned cw[NW];        // rowA2[13-w]: measurement parity masks per wire
    unsigned swzP0[32];     // swz2(combos of colAinv[5..9])  (p0 store offsets)
    unsigned swzF5[32];     // swz2(combos of colAinv[0..4])  (final-pass offsets)
    int fw5[NW];            // 5-bit WHT frequency per wire
};

constexpr unsigned ctswz2(unsigned y) { return y ^ ((y >> 5) & 0xFu); }
constexpr int ctpar(unsigned v) { int p = 0; while (v) { p ^= (int)(v & 1u); v >>= 1; } return p; }

constexpr CT buildCT() {
    CT g{};
    unsigned R[NW] = {};
    for (int j = 0; j < NW; ++j) R[j] = 1u << j;
    // CNOT(w,w+1) w=0..12 then CNOT(13,0); wire w <-> bit 13-w
    for (int w = 0; w < NW - 1; ++w) R[NW - 2 - w] ^= R[NW - 1 - w];
    R[NW - 1] ^= R[0];
    for (int j = 0; j < NW; ++j) g.rowA[j] = R[j];
    unsigned aug[NW] = {};
    for (int j = 0; j < NW; ++j) aug[j] = R[j] | (1u << (NW + j));
    for (int col = 0; col < NW; ++col) {
        int piv = -1;
        for (int rr = col; rr < NW; ++rr)
            if ((aug[rr] >> col) & 1u) { piv = rr; break; }
        unsigned t = aug[col]; aug[col] = aug[piv]; aug[piv] = t;
        for (int rr = 0; rr < NW; ++rr)
            if (rr != col && ((aug[rr] >> col) & 1u)) aug[rr] ^= aug[col];
    }
    for (int bc = 0; bc < NW; ++bc) {
        unsigned mc = 0;
        for (int j = 0; j < NW; ++j) mc |= ((aug[j] >> (NW + bc)) & 1u) << j;
        g.colAinv[bc] = mc;
    }
    for (int w = 0; w < NW; ++w) {
        const int k = 13 - w;
        unsigned rr = 0;
        for (int j = 0; j < NW; ++j) if ((R[k] >> j) & 1u) rr ^= R[j];
        g.cw[w] = rr;
    }
    for (unsigned u = 0; u < 32; ++u) {
        unsigned M0 = 0, M1 = 0;
        for (int i = 0; i < 5; ++i) if ((u >> i) & 1u) { M0 ^= g.colAinv[5 + i]; M1 ^= g.colAinv[i]; }
        g.swzP0[u] = ctswz2(M0);
        g.swzF5[u] = ctswz2(M1);
    }
    for (int w = 0; w < NW; ++w) {
        int f = 0;
        for (int i = 0; i < 5; ++i) f |= ctpar(g.colAinv[i] & g.cw[w]) << i;
        g.fw5[w] = f;
    }
    return g;
}
constexpr CT CD = buildCT();

// ---- compile-time validation ----
constexpr bool checkPass(unsigned posmask, int b0, int k) {
    unsigned v[NW] = {}; int n = 0;
    for (int p = 0; p < NW; ++p) if ((posmask >> p) & 1u) v[n++] = 1u << p;
    for (int i = 0; i < k; ++i) v[n++] = CD.colAinv[b0 + i];
    if (n != NW) return false;
    int rank = 0;
    for (int bit = 0; bit < NW; ++bit) {
        int piv = -1;
        for (int i = rank; i < NW; ++i) if ((v[i] >> bit) & 1u) { piv = i; break; }
        if (piv < 0) continue;
        unsigned t = v[rank]; v[rank] = v[piv]; v[piv] = t;
        for (int i = 0; i < NW; ++i) if (i != rank && ((v[i] >> bit) & 1u)) v[i] ^= v[rank];
        ++rank;
    }
    return rank == NW;
}
static_assert(checkPass(0x001F, 5, 9), "p0 transversal");
static_assert(checkPass(0x3FE0, 0, 5), "final transversal");
static_assert(CD.colAinv[1] == 0x3 && CD.colAinv[2] == 0x6 && CD.colAinv[3] == 0xC &&
              CD.colAinv[4] == 0x18 && CD.colAinv[5] == 0x30 && CD.colAinv[6] == 0x60 &&
              CD.colAinv[7] == 0xC0 && CD.colAinv[8] == 0x180 && CD.colAinv[9] == 0x300 &&
              CD.colAinv[10] == 0x600 && CD.colAinv[11] == 0xC00 &&
              CD.colAinv[12] == 0x1800 && CD.colAinv[13] == 0x3000, "chain masks");
static_assert((CD.rowA[5] & 0x1F) == 0 && (CD.rowA[6] & 0x1F) == 0 && (CD.rowA[7] & 0x1F) == 0 &&
              (CD.rowA[8] & 0x1F) == 0 && (CD.rowA[9] & 0x1F) == 0 && (CD.rowA[10] & 0x1F) == 0 &&
              (CD.rowA[11] & 0x1F) == 0 && (CD.rowA[12] & 0x1F) == 0 &&
              (CD.rowA[13] & 0x1F) == 0x1F, "table bases");
static_assert((CD.rowA[0] & 0x3FE0) == 0x3FE0 && (CD.rowA[1] & 0x3FE0) == 0x3FE0 &&
              (CD.rowA[2] & 0x3FE0) == 0x3FE0 && (CD.rowA[3] & 0x3FE0) == 0x3FE0 &&
              (CD.rowA[4] & 0x3FE0) == 0x3FE0, "final bases");

template<int V> struct IC { static constexpr int v = V; };

// ==================== device helpers ====================
__device__ __forceinline__ float2 cmul(float2 a, float2 b) {
    return make_float2(fmaf(a.x, b.x, -a.y * b.y), fmaf(a.x, b.y, a.y * b.x));
}
__device__ __forceinline__ float2 cmadd(float2 acc, float2 a, float2 b) {
    acc.x = fmaf(a.x, b.x, fmaf(-a.y, b.y, acc.x));
    acc.y = fmaf(a.x, b.y, fmaf(a.y, b.x, acc.y));
    return acc;
}
__device__ __forceinline__ int dswz2(int y) { return y ^ ((y >> 5) & 0xF); }

__device__ __forceinline__ void bfly(float2& a0, float2& a1,
                                     float2 E00, float2 E01, float2 E10, float2 E11) {
    float2 n0 = cmul(E00, a0); n0 = cmadd(n0, E01, a1);
    float2 n1 = cmul(E10, a0); n1 = cmadd(n1, E11, a1);
    a0 = n0; a1 = n1;
}
__device__ __forceinline__ float2 shflx(float2 v, int m) {
    float2 o;
    o.x = __shfl_xor_sync(0xFFFFFFFFu, v.x, m);
    o.y = __shfl_xor_sync(0xFFFFFFFFu, v.y, m);
    return o;
}

// p0 store: 16 amplitudes of half HALF
template<int HALF, int J>
__device__ __forceinline__ void p0_half(float2* st, int zb, float2 P, const float2* tab) {
    st[zb ^ IC<(int)CD.swzP0[HALF * 16 + J]>::v] = cmul(P, tab[4 * J]);
    if constexpr (J < 15) p0_half<HALF, J + 1>(st, zb, P, tab);
}
// final-pass load of half HALF
template<int HALF, int J>
__device__ __forceinline__ void f_half(float2 (&amp)[16], const float2* st, int zb) {
    amp[J] = st[zb ^ IC<(int)CD.swzF5[HALF * 16 + J]>::v];
    if constexpr (J < 15) f_half<HALF, J + 1>(amp, st, zb);
}

template<int W>
__device__ __forceinline__ int signw(int r) {
    int v = (__popc(r & IC<(int)CD.cw[W]>::v) & 1) << W;
    if constexpr (W > 0) v |= signw<W - 1>(r);
    return v;
}
// per-wire: owned threads contribute +/-Wv[f&15], others 0; warp-reduce; lane0 stores
template<int W>
__device__ __forceinline__ void redw(float (*wsum)[NW], int swv, const float (&Wv)[16],
                                     int halfu, int lane, int warp) {
    float tv = (IC<(CD.fw5[W] >> 4)>::v == halfu) ? Wv[IC<(CD.fw5[W] & 15)>::v] : 0.0f;
    tv = __int_as_float(__float_as_int(tv) ^ ((((unsigned)swv >> W) & 1u) << 31));
#pragma unroll
    for (int off = 16; off; off >>= 1) tv += __shfl_down_sync(0xFFFFFFFFu, tv, off);
    if (lane == 0) wsum[warp][W] = tv;
    if constexpr (W < NW - 1) redw<W + 1>(wsum, swv, Wv, halfu, lane, warp);
}

// ==================== kernel ====================
__global__ __launch_bounds__(NTHREADS, 1)
void qsim_kernel(const float* __restrict__ x, const float* __restrict__ params,
                 float* __restrict__ out)
{
    extern __shared__ float2 state[];      // 16384 float2 = 128 KB (also build scratch)
    __shared__ float2 m0V[NW][4];          // layer-0 fused 2x2 (incl. x)
    __shared__ float2 m1V[NW][4];          // layer-1 fused 2x2
    __shared__ float2 T[512][4];           // hoisted-gate table: [u][r4*2+p]
    __shared__ float wsum[NWARPS][NW];

    const int tid = threadIdx.x;
    const int b = blockIdx.x;

    // ---- fused gate matrices: M = RX * RZ * RY (layer 0 folds in x)
    if (tid < 2 * NW) {
        const int l = tid / NW, w = tid % NW;
        const float* pp = params + (l * NW + w) * 3;
        float th = pp[0] + (l == 0 ? x[b * NW + w] : 0.0f);
        float s, c;   sincosf(0.5f * th, &s, &c);
        float sz, cz; sincosf(0.5f * pp[1], &sz, &cz);
        float sx, cx; sincosf(0.5f * pp[2], &sx, &cx);
        float2 r00 = make_float2(c * cz, -c * sz);
        float2 r01 = make_float2(-s * cz, s * sz);
        float2 r10 = make_float2(s * cz, s * sz);
        float2 r11 = make_float2(c * cz, c * sz);
        float2 (*dst)[4] = (l == 0) ? m0V : m1V;
        dst[w][0] = make_float2(cx * r00.x + sx * r10.y, cx * r00.y - sx * r10.x);
        dst[w][1] = make_float2(cx * r01.x + sx * r11.y, cx * r01.y - sx * r11.x);
        dst[w][2] = make_float2(sx * r00.y + cx * r10.x, -sx * r00.x + cx * r10.y);
        dst[w][3] = make_float2(sx * r01.y + cx * r11.x, -sx * r01.x + cx * r11.y);
    }
    __syncthreads();

    // ---- Table build: u = tid&511, variant a(=r4) = tid>>9.
    //      Encoding over y bits 4..13, then 9 gate stages (wires 8..0) in u-space.
    {
        const int u = tid & 511, a = tid >> 9;
        const int u0 = u & 1, u1 = (u >> 1) & 1, u2 = (u >> 2) & 1, u3 = (u >> 3) & 1,
                  u4 = (u >> 4) & 1, u5 = (u >> 5) & 1, u6 = (u >> 6) & 1,
                  u7 = (u >> 7) & 1, u8 = (u >> 8) & 1;
        float2 cc = m0V[8][(u0 ^ u1) ? 2 : 0];
        cc = cmul(cc, m0V[7][(u1 ^ u2) ? 2 : 0]);
        cc = cmul(cc, m0V[6][(u2 ^ u3) ? 2 : 0]);
        cc = cmul(cc, m0V[5][(u3 ^ u4) ? 2 : 0]);
        cc = cmul(cc, m0V[4][(u4 ^ u5) ? 2 : 0]);
        cc = cmul(cc, m0V[3][(u5 ^ u6) ? 2 : 0]);
        cc = cmul(cc, m0V[2][(u6 ^ u7) ? 2 : 0]);
        cc = cmul(cc, m0V[1][(u7 ^ u8) ? 2 : 0]);
        cc = cmul(cc, m0V[0][u8 ? 2 : 0]);
        cc = cmul(cc, m0V[9][(u0 ^ a) ? 2 : 0]);
        // stages 0..4: in-warp shuffle butterflies (u bits 0..4 = lane bits)
#pragma unroll
        for (int k = 0; k < 5; ++k) {
            const int w = 8 - k;
            const float2 other = shflx(cc, 1 << k);
            const int hi = (u >> k) & 1;
            const float2 Er0 = m1V[w][hi ? 2 : 0];
            const float2 Er1 = m1V[w][hi ? 3 : 1];
            const float2 f1 = hi ? other : cc;
            const float2 f2 = hi ? cc : other;
            float2 n = cmul(Er0, f1); n = cmadd(n, Er1, f2);
            cc = n;
        }
        // stages 5..7: cross-warp via scratch in `state`
#pragma unroll
        for (int k = 5; k < 8; ++k) {
            __syncthreads();
            state[tid] = cc;
            __syncthreads();
            const float2 other = state[tid ^ (1 << k)];
            const int w = 8 - k;
            const int hi = (u >> k) & 1;
            const float2 Er0 = m1V[w][hi ? 2 : 0];
            const float2 Er1 = m1V[w][hi ? 3 : 1];
            const float2 f1 = hi ? other : cc;
            const float2 f2 = hi ? cc : other;
            float2 n = cmul(Er0, f1); n = cmadd(n, Er1, f2);
            cc = n;
        }
        // stage 8 (wire 0): fork p variants (label swap)
        __syncthreads();
        state[tid] = cc;
        __syncthreads();
        {
            const float2 other = state[tid ^ 256];
            const int hi = u8;
            const float2 f1 = hi ? other : cc;
            const float2 f2 = hi ? cc : other;
            const int i0 = hi ? 2 : 0, i1 = hi ? 3 : 1;
            float2 n = cmul(m1V[0][i0], f1); n = cmadd(n, m1V[0][i1], f2);
            float2 sv = cmul(m1V[0][i0 ^ 3], f1); sv = cmadd(sv, m1V[0][i1 ^ 3], f2);
            T[u][a * 2] = n;
            T[u][a * 2 + 1] = sv;
        }
    }
    __syncthreads();

    // ---- Pass 0: state[y] = P_r * T[u][v]  (9 of 14 gates already in table)
    {
        const int r = tid & 31;              // y bits 0..4
        const int hh = tid >> 5;             // 0..31
        const int h = hh & 15, half = hh >> 4;
        const int pp = __popc(r) & 1;
        const int r4 = (r >> 4) & 1;
        const int v = r4 * 2 + pp;
        const float2 q0 = cmul(m0V[13][(r & 1) ? 2 : 0], m0V[12][(r & 2) ? 2 : 0]);
        const float2 q1 = cmul(m0V[11][(r & 4) ? 2 : 0], m0V[10][(r & 8) ? 2 : 0]);
        const float2 P = cmul(q0, q1);
        int Mh = 0;
        if (h & 1) Mh ^= IC<(int)CD.colAinv[10]>::v;
        if (h & 2) Mh ^= IC<(int)CD.colAinv[11]>::v;
        if (h & 4) Mh ^= IC<(int)CD.colAinv[12]>::v;
        if (h & 8) Mh ^= IC<(int)CD.colAinv[13]>::v;
        const int zb = dswz2(r ^ Mh);
        const float2* tab = &T[(h << 5) + half * 16][0] + v;
        if (half) p0_half<1, 0>(state, zb, P, tab);
        else      p0_half<0, 0>(state, zb, P, tab);
    }
    __syncthreads();

    // ---- Final pass: gates on virtual bits 0..4 (wires 13..9) + measurement.
    //      Lane pair (tid^1) splits a 32-amp coset by u bit 4.
    {
        const int halfu = tid & 1;
        const int cc = tid >> 1;               // coset index: y bits 5..13
        const int zb = dswz2(cc << 5);
        const int sw = (__popc(cc) & 1) ? 3 : 0;
        float2 amp[16];
        if (halfu) f_half<1, 0>(amp, state, zb);
        else       f_half<0, 0>(amp, state, zb);
        // cross gate: wire 9 (u bit 4) via shfl.xor(1), half-butterfly per thread
        {
            const float2 Ea = m1V[9][(halfu ? 2 : 0) ^ sw];
            const float2 Eb = m1V[9][(halfu ? 3 : 1) ^ sw];
#pragma unroll
            for (int j = 0; j < 16; ++j) {
                const float2 other = shflx(amp[j], 1);
                const float2 f1 = halfu ? other : amp[j];
                const float2 f2 = halfu ? amp[j] : other;
                float2 n = cmul(Ea, f1); n = cmadd(n, Eb, f2);
                amp[j] = n;
            }
        }
        // local gates: wires 13..10 on u bits 0..3
#pragma unroll
        for (int i = 0; i < 4; ++i) {
            const int w = 13 - i;
            const float2 E00 = m1V[w][0 ^ sw], E01 = m1V[w][1 ^ sw];
            const float2 E10 = m1V[w][2 ^ sw], E11 = m1V[w][3 ^ sw];
#pragma unroll
            for (int u = 0; u < 16; ++u) {
                if (u & (1 << i)) continue;
                bfly(amp[u], amp[u | (1 << i)], E00, E01, E10, E11);
            }
        }
        // probabilities + 4 local WHT levels + cross level via shuffle
        float Wv[16];
#pragma unroll
        for (int u = 0; u < 16; ++u)
            Wv[u] = fmaf(amp[u].x, amp[u].x, amp[u].y * amp[u].y);
#pragma unroll
        for (int d = 1; d < 16; d <<= 1) {
#pragma unroll
            for (int u = 0; u < 16; ++u) {
                if (u & d) continue;
                const float a = Wv[u], bb = Wv[u | d];
                Wv[u] = a + bb; Wv[u | d] = a - bb;
            }
        }
#pragma unroll
        for (int f = 0; f < 16; ++f) {
            const float o = __shfl_xor_sync(0xFFFFFFFFu, Wv[f], 1);
            Wv[f] = halfu ? (o - Wv[f]) : (Wv[f] + o);
        }
        const int swv = signw<NW - 1>(cc << 5);
        const int lane = tid & 31, warp = tid >> 5;
        redw<0>(wsum, swv, Wv, halfu, lane, warp);
    }
    __syncthreads();

    if (tid < NW) {
        float s = 0.0f;
#pragma unroll
        for (int q = 0; q < NWARPS; ++q) s += wsum[q][tid];
        out[b * NW + tid] = s;
    }
}

// ==================== host side ====================
extern "C" void kernel_launch(void* const* d_in, const int* in_sizes, int n_in,
                              void* d_out, int out_size)
{
    int i_x = 0, i_p = 1;
    if (n_in >= 2 && in_sizes[0] == 2 * NW * 3) { i_x = 1; i_p = 0; }
    const float* x = (const float*)d_in[i_x];
    const float* params = (const float*)d_in[i_p];
    float* out = (float*)d_out;

    const int batch = in_sizes[i_x] / NW;

    cudaFuncSetAttribute(qsim_kernel, cudaFuncAttributeMaxDynamicSharedMemorySize,
                         NSTATE * sizeof(float2));
    qsim_kernel<<<batch, NTHREADS, NSTATE * sizeof(float2)>>>(x, params, out);
}